// round 13
// baseline (speedup 1.0000x reference)
#include <cuda_runtime.h>
#include <cuda_fp16.h>
#include <math.h>

// ---------------- problem constants ----------------
#define S_LEN    4096
#define DMODEL   1024
#define N_HEADS  16
#define HEAD_DIM 64
#define NX (S_LEN * DMODEL)
#define NW (DMODEL * DMODEL)

// ---------------- scratch: single-plane fp16 ----------------
__device__ unsigned short g_x16[NX];
__device__ unsigned short g_q16[NX];
__device__ unsigned short g_k16[NX];
__device__ unsigned short g_v16[NX];
__device__ unsigned short g_c16[NX];
__device__ unsigned short g_Wq16[NW];
__device__ unsigned short g_Wk16[NW];
__device__ unsigned short g_Wv16[NW];
__device__ unsigned short g_Wo16[NW];

// ---------------- small helpers ----------------
__device__ __forceinline__ unsigned smem_u32(const void* p) {
    unsigned a;
    asm("{ .reg .u64 t; cvta.to.shared.u64 t, %1; cvt.u32.u64 %0, t; }" : "=r"(a) : "l"(p));
    return a;
}
__device__ __forceinline__ void cp16(unsigned dst, const void* src) {
    asm volatile("cp.async.cg.shared.global [%0], [%1], 16;" :: "r"(dst), "l"(src));
}
__device__ __forceinline__ void ldm_x4(unsigned* r, unsigned addr) {
    asm volatile("ldmatrix.sync.aligned.m8n8.x4.shared.b16 {%0,%1,%2,%3}, [%4];"
                 : "=r"(r[0]), "=r"(r[1]), "=r"(r[2]), "=r"(r[3]) : "r"(addr));
}
__device__ __forceinline__ void ldm_x4t(unsigned* r, unsigned addr) {
    asm volatile("ldmatrix.sync.aligned.m8n8.x4.trans.shared.b16 {%0,%1,%2,%3}, [%4];"
                 : "=r"(r[0]), "=r"(r[1]), "=r"(r[2]), "=r"(r[3]) : "r"(addr));
}
__device__ __forceinline__ void mma_f16(float* d, const unsigned* a, const unsigned* b) {
    asm volatile(
        "mma.sync.aligned.m16n8k16.row.col.f32.f16.f16.f32 "
        "{%0,%1,%2,%3}, {%4,%5,%6,%7}, {%8,%9}, {%0,%1,%2,%3};"
        : "+f"(d[0]), "+f"(d[1]), "+f"(d[2]), "+f"(d[3])
        : "r"(a[0]), "r"(a[1]), "r"(a[2]), "r"(a[3]), "r"(b[0]), "r"(b[1]));
}
__device__ __forceinline__ unsigned packf16(float lo, float hi) {
    unsigned r;
    asm("cvt.rn.f16x2.f32 %0, %1, %2;" : "=r"(r) : "f"(hi), "f"(lo));
    return r;
}
__device__ __forceinline__ float ex2(float x) {
    float y; asm("ex2.approx.ftz.f32 %0, %1;" : "=f"(y) : "f"(x)); return y;
}
__device__ __forceinline__ float rcp(float x) {
    float y; asm("rcp.approx.ftz.f32 %0, %1;" : "=f"(y) : "f"(x)); return y;
}

// ---------------- convert fp32 -> fp16 (x + 4 weight matrices, one launch) ----------------
__global__ __launch_bounds__(256)
void to_f16_all(const float* __restrict__ x,
                const float* __restrict__ wq, const float* __restrict__ wk,
                const float* __restrict__ wv, const float* __restrict__ wo)
{
    const int b = blockIdx.x;
    const float* src;
    unsigned short* dst;
    int i;
    if (b < 4096) {
        src = x; dst = g_x16;
        i = (b * 256 + threadIdx.x) * 4;
    } else {
        const int wsel = (b - 4096) >> 10;
        src = (wsel == 0) ? wq : (wsel == 1) ? wk : (wsel == 2) ? wv : wo;
        dst = (wsel == 0) ? g_Wq16 : (wsel == 1) ? g_Wk16 : (wsel == 2) ? g_Wv16 : g_Wo16;
        i = (((b - 4096) & 1023) * 256 + threadIdx.x) * 4;
    }
    float4 a = *(const float4*)(src + i);
    *(uint2*)(dst + i) = make_uint2(packf16(a.x, a.y), packf16(a.z, a.w));
}

// ---------------- fp16 GEMM: C = A @ B^T + bias ----------------
// 256x128 CTA tile, BK=32, 8 warps (4x2), warp tile 64x64.
// 4-stage cp.async, single sync per chunk, frag double-buffering, 1 CTA/SM.
#define ROWB    80
#define APLANE  (256 * ROWB)             // 20480
#define BPLANE  (128 * ROWB)             // 10240
#define STAGE   (APLANE + BPLANE)        // 30720
#define NSTAGE  4
#define GSMEM   (NSTAGE * STAGE)         // 122880
#define NCHUNK  32

struct Frags {
    unsigned a[4][4];
    unsigned b[4][4];
};

__device__ __forceinline__
void load_frags(Frags& f, unsigned sA, unsigned sB, unsigned ka,
                int a_row, unsigned a_coff, int b_row, unsigned b_coff)
{
#pragma unroll
    for (int pr = 0; pr < 4; pr++)
        ldm_x4(f.b[pr], sB + (unsigned)((b_row + pr * 16) * ROWB) + ka + b_coff);
#pragma unroll
    for (int mt = 0; mt < 4; mt++)
        ldm_x4(f.a[mt], sA + (unsigned)((a_row + mt * 16) * ROWB) + ka + a_coff);
}

__device__ __forceinline__
void do_mma(float acc[4][8][4], const Frags& f)
{
#pragma unroll
    for (int mt = 0; mt < 4; mt++)
#pragma unroll
        for (int pr = 0; pr < 4; pr++)
#pragma unroll
            for (int half = 0; half < 2; half++)
                mma_f16(acc[mt][pr * 2 + half], f.a[mt], &f.b[pr][half * 2]);
}

__device__ __forceinline__
void gemm_body(char* smem,
               const unsigned short* __restrict__ A, const unsigned short* __restrict__ B,
               const float* __restrict__ bias, int bm, int bn,
               int mode, float* __restrict__ C, unsigned short* __restrict__ Ch)
{
    const int t = threadIdx.x, lane = t & 31, wid = t >> 5;
    const int wm = wid >> 1, wn = wid & 1;

    float acc[4][8][4];
#pragma unroll
    for (int mt = 0; mt < 4; mt++)
#pragma unroll
        for (int nt = 0; nt < 8; nt++)
#pragma unroll
            for (int r = 0; r < 4; r++) acc[mt][nt][r] = 0.f;

    const int r0 = t >> 2, s0 = t & 3;

#define ISSUE(cc)                                                                 \
    {                                                                             \
        char* sbuf = smem + ((cc) & (NSTAGE - 1)) * STAGE;                        \
        const int gk = (cc) * 32 + s0 * 8;                                        \
        const unsigned short* ga = A + (size_t)(bm + r0) * DMODEL + gk;           \
        const unsigned short* gb = B + (size_t)(bn + r0) * DMODEL + gk;           \
        unsigned da = smem_u32(sbuf + s0 * 16);                                   \
        unsigned db = smem_u32(sbuf + APLANE + s0 * 16);                          \
        cp16(da + r0 * ROWB,         ga);                                         \
        cp16(da + (r0 + 64) * ROWB,  ga + (size_t)64  * DMODEL);                  \
        cp16(da + (r0 + 128) * ROWB, ga + (size_t)128 * DMODEL);                  \
        cp16(da + (r0 + 192) * ROWB, ga + (size_t)192 * DMODEL);                  \
        cp16(db + r0 * ROWB,         gb);                                         \
        cp16(db + (r0 + 64) * ROWB,  gb + (size_t)64  * DMODEL);                  \
        asm volatile("cp.async.commit_group;" ::: "memory");                      \
    }

    ISSUE(0); ISSUE(1); ISSUE(2);

    const int a_row = wm * 64 + (lane & 15);
    const unsigned a_coff = (lane >> 4) * 16;
    const int b_row = wn * 64 + (lane & 7) + ((lane >> 4) << 3);
    const unsigned b_coff = ((lane >> 3) & 1) * 16;

    // prologue: stages 0 and 1 arrived, then load frags(chunk0, ks0)
    asm volatile("cp.async.wait_group 1;" ::: "memory");
    __syncthreads();

    Frags f0, f1;
    {
        const unsigned sA = smem_u32(smem);
        load_frags(f0, sA, sA + APLANE, 0, a_row, a_coff, b_row, b_coff);
    }

    for (int c = 0; c < NCHUNK; c++) {
        // invariant: stages c and c+1 visible; f0 = (c, ks0)
        if (c + 3 < NCHUNK) ISSUE(c + 3);   // buffer (c+3)%4 == (c-1)%4, freed by last barrier

        const unsigned sA = smem_u32(smem + (c & (NSTAGE - 1)) * STAGE);
        const unsigned sB = sA + APLANE;

        load_frags(f1, sA, sB, 32, a_row, a_coff, b_row, b_coff);   // (c, ks1)
        do_mma(acc, f0);                                            // (c, ks0)

        if (c + 1 < NCHUNK) {
            const unsigned nA = smem_u32(smem + ((c + 1) & (NSTAGE - 1)) * STAGE);
            load_frags(f0, nA, nA + APLANE, 0, a_row, a_coff, b_row, b_coff); // (c+1, ks0)
        }
        do_mma(acc, f1);                                            // (c, ks1)

        if (c + 1 < NCHUNK) {
            if (c + 3 < NCHUNK) {
                asm volatile("cp.async.wait_group 1;" ::: "memory");
            } else {
                asm volatile("cp.async.wait_group 0;" ::: "memory");
            }
            __syncthreads();
        }
    }
#undef ISSUE

    // ---- epilogue ----
    const int er = lane >> 2, ec = (lane & 3) * 2;
#pragma unroll
    for (int mt = 0; mt < 4; mt++) {
        const int row = bm + wm * 64 + mt * 16 + er;
#pragma unroll
        for (int nt = 0; nt < 8; nt++) {
            const int col = bn + wn * 64 + nt * 8 + ec;
            const float b0 = bias[col], b1 = bias[col + 1];
            float v0 = acc[mt][nt][0] + b0, v1 = acc[mt][nt][1] + b1;
            float v2 = acc[mt][nt][2] + b0, v3 = acc[mt][nt][3] + b1;
            if (mode == 0) {
                *(float2*)&C[(size_t)row * DMODEL + col] = make_float2(v0, v1);
                *(float2*)&C[(size_t)(row + 8) * DMODEL + col] = make_float2(v2, v3);
            } else {
                *(unsigned*)&Ch[(size_t)row * DMODEL + col] = packf16(v0, v1);
                *(unsigned*)&Ch[(size_t)(row + 8) * DMODEL + col] = packf16(v2, v3);
            }
        }
    }
}

// ---- fused QKV projection: grid (24, 16); blockIdx.x/8 selects Q/K/V ----
__global__ __launch_bounds__(256, 1)
void gemm_qkv(const float* __restrict__ bq, const float* __restrict__ bk,
              const float* __restrict__ bv)
{
    extern __shared__ char smem[];
    const int which = blockIdx.x >> 3;
    const int bn = (blockIdx.x & 7) * 128;
    const int bm = blockIdx.y * 256;
    const unsigned short* B = (which == 0) ? g_Wq16 : (which == 1) ? g_Wk16 : g_Wv16;
    const float* bias = (which == 0) ? bq : (which == 1) ? bk : bv;
    unsigned short* Ch = (which == 0) ? g_q16 : (which == 1) ? g_k16 : g_v16;
    gemm_body(smem, g_x16, B, bias, bm, bn, 1, nullptr, Ch);
}

// ---- output projection: ctx(f16) @ Wo^T + bo -> fp32 out ----
__global__ __launch_bounds__(256, 1)
void gemm_out(const float* __restrict__ bo, float* __restrict__ out)
{
    extern __shared__ char smem[];
    gemm_body(smem, g_c16, g_Wo16, bo,
              blockIdx.y * 256, blockIdx.x * 128, 0, out, nullptr);
}

// ---------------- tensorized sliding-window attention (fp16) ----------------
// grid (S/128, H), 256 threads (8 warps). Warp w: 16 query rows (local 16w..16w+15),
// keys local [16w, 16w+143] of a shared 256-row K/V tile (9 pr-tiles of 16).
#define AT_Q   128
#define AT_KW  256
#define AROWB  144
#define A_SQ   0
#define A_SK   (AT_Q * AROWB)               // 18432
#define A_SV   (A_SK + AT_KW * AROWB)       // 55296
#define A_SMEM (A_SV + AT_KW * AROWB)       // 92160 -> 2 CTAs/SM

__global__ __launch_bounds__(256, 2)
void attn_mma()
{
    extern __shared__ char smem[];
    const unsigned sb = smem_u32(smem);
    const int t = threadIdx.x, lane = t & 31, w = t >> 5;
    const int h = blockIdx.y;
    const int q0 = blockIdx.x * AT_Q;
    const int j0 = q0 - 64;
    const int col = h * HEAD_DIM;

    // ---- load Q (128x64) ----
#pragma unroll
    for (int i = 0; i < 4; i++) {
        int idx = t + i * 256;               // 0..1023
        int r = idx >> 3, sg = idx & 7;
        *(uint4*)(smem + A_SQ + r * AROWB + sg * 16) =
            *(const uint4*)(g_q16 + (size_t)(q0 + r) * DMODEL + col + sg * 8);
    }
    // ---- load K,V window (256x64), zero-fill out of range ----
#pragma unroll
    for (int i = 0; i < 8; i++) {
        int idx = t + i * 256;               // 0..2047
        int r = idx >> 3, sg = idx & 7;
        int j = j0 + r;
        uint4 kv = make_uint4(0,0,0,0), vv = kv;
        if ((unsigned)j < (unsigned)S_LEN) {
            size_t go = (size_t)j * DMODEL + col + sg * 8;
            kv = *(const uint4*)(g_k16 + go);
            vv = *(const uint4*)(g_v16 + go);
        }
        unsigned so = r * AROWB + sg * 16;
        *(uint4*)(smem + A_SK + so) = kv;
        *(uint4*)(smem + A_SV + so) = vv;
    }
    __syncthreads();

    // ---- S = Q K^T over warp's 144-key window ----
    float sc[18][4];
#pragma unroll
    for (int nt = 0; nt < 18; nt++)
#pragma unroll
        for (int r = 0; r < 4; r++) sc[nt][r] = 0.f;

    const int lk0 = w * 16;
    const unsigned a_base = (unsigned)((w * 16 + (lane & 15)) * AROWB) + ((lane >> 4) << 4);
    const int b_lrow = (lane & 7) + ((lane >> 4) << 3);
    const unsigned b_coff = ((lane >> 3) & 1) << 4;

#pragma unroll
    for (int kc = 0; kc < 4; kc++) {
        unsigned afr[4];
        ldm_x4(afr, sb + A_SQ + a_base + kc * 32);
#pragma unroll
        for (int pr = 0; pr < 9; pr++) {
            unsigned bfr[4];
            ldm_x4(bfr, sb + A_SK + (unsigned)((lk0 + pr * 16 + b_lrow) * AROWB) + kc * 32 + b_coff);
            mma_f16(sc[pr * 2],     afr, &bfr[0]);
            mma_f16(sc[pr * 2 + 1], afr, &bfr[2]);
        }
    }

    // ---- mask + softmax ----
    const int er = lane >> 2, ec = (lane & 3) * 2;
    const float SC = 0.125f * 1.44269504088896f;
    float m0 = -1e30f, m1 = -1e30f;
#pragma unroll
    for (int nt = 0; nt < 18; nt++) {
        const int d = nt * 8 + ec;
        const int j = j0 + lk0 + d;
        bool v00 = ((unsigned)(d     - er)     <= 128u) && ((unsigned)j       < (unsigned)S_LEN);
        bool v01 = ((unsigned)(d + 1 - er)     <= 128u) && ((unsigned)(j + 1) < (unsigned)S_LEN);
        bool v10 = ((unsigned)(d     - er - 8) <= 128u) && ((unsigned)j       < (unsigned)S_LEN);
        bool v11 = ((unsigned)(d + 1 - er - 8) <= 128u) && ((unsigned)(j + 1) < (unsigned)S_LEN);
        sc[nt][0] = v00 ? sc[nt][0] * SC : -1e30f;
        sc[nt][1] = v01 ? sc[nt][1] * SC : -1e30f;
        sc[nt][2] = v10 ? sc[nt][2] * SC : -1e30f;
        sc[nt][3] = v11 ? sc[nt][3] * SC : -1e30f;
        m0 = fmaxf(m0, fmaxf(sc[nt][0], sc[nt][1]));
        m1 = fmaxf(m1, fmaxf(sc[nt][2], sc[nt][3]));
    }
    m0 = fmaxf(m0, __shfl_xor_sync(0xffffffffu, m0, 1));
    m0 = fmaxf(m0, __shfl_xor_sync(0xffffffffu, m0, 2));
    m1 = fmaxf(m1, __shfl_xor_sync(0xffffffffu, m1, 1));
    m1 = fmaxf(m1, __shfl_xor_sync(0xffffffffu, m1, 2));

    float s0 = 0.f, s1 = 0.f;
#pragma unroll
    for (int nt = 0; nt < 18; nt++) {
        sc[nt][0] = ex2(sc[nt][0] - m0);
        sc[nt][1] = ex2(sc[nt][1] - m0);
        sc[nt][2] = ex2(sc[nt][2] - m1);
        sc[nt][3] = ex2(sc[nt][3] - m1);
        s0 += sc[nt][0] + sc[nt][1];
        s1 += sc[nt][2] + sc[nt][3];
    }
    s0 += __shfl_xor_sync(0xffffffffu, s0, 1);
    s0 += __shfl_xor_sync(0xffffffffu, s0, 2);
    s1 += __shfl_xor_sync(0xffffffffu, s1, 1);
    s1 += __shfl_xor_sync(0xffffffffu, s1, 2);
    const float inv0 = rcp(s0), inv1 = rcp(s1);

    // ---- O = P V over the same 144-key window ----
    float oa[8][4];
#pragma unroll
    for (int nt = 0; nt < 8; nt++)
#pragma unroll
        for (int r = 0; r < 4; r++) oa[nt][r] = 0.f;

#pragma unroll
    for (int kc = 0; kc < 9; kc++) {
        unsigned ph[4];
        ph[0] = packf16(sc[2 * kc][0],     sc[2 * kc][1]);
        ph[1] = packf16(sc[2 * kc][2],     sc[2 * kc][3]);
        ph[2] = packf16(sc[2 * kc + 1][0], sc[2 * kc + 1][1]);
        ph[3] = packf16(sc[2 * kc + 1][2], sc[2 * kc + 1][3]);
#pragma unroll
        for (int dt = 0; dt < 4; dt++) {
            unsigned vh[4];
            unsigned voff = (unsigned)((lk0 + kc * 16 + (lane & 15)) * AROWB) + dt * 32 + ((lane >> 4) << 4);
            ldm_x4t(vh, sb + A_SV + voff);
            mma_f16(oa[2 * dt],     ph, &vh[0]);
            mma_f16(oa[2 * dt + 1], ph, &vh[2]);
        }
    }

    // ---- normalize + write ctx as fp16 ----
    const int row0 = q0 + w * 16 + er;
#pragma unroll
    for (int nt = 0; nt < 8; nt++) {
        const int oc = col + nt * 8 + ec;
        float v0 = oa[nt][0] * inv0, v1 = oa[nt][1] * inv0;
        float v2 = oa[nt][2] * inv1, v3 = oa[nt][3] * inv1;
        *(unsigned*)&g_c16[(size_t)row0 * DMODEL + oc] = packf16(v0, v1);
        *(unsigned*)&g_c16[(size_t)(row0 + 8) * DMODEL + oc] = packf16(v2, v3);
    }
}

// ---------------- launch ----------------
extern "C" void kernel_launch(void* const* d_in, const int* in_sizes, int n_in,
                              void* d_out, int out_size)
{
    const float* x  = (const float*)d_in[0];
    const float* Wq = (const float*)d_in[1];
    const float* bq = (const float*)d_in[2];
    const float* Wk = (const float*)d_in[3];
    const float* bk = (const float*)d_in[4];
    const float* Wv = (const float*)d_in[5];
    const float* bv = (const float*)d_in[6];
    const float* Wo = (const float*)d_in[7];
    const float* bo = (const float*)d_in[8];
    float* out = (float*)d_out;

    cudaFuncSetAttribute(gemm_qkv, cudaFuncAttributeMaxDynamicSharedMemorySize, GSMEM);
    cudaFuncSetAttribute(gemm_out, cudaFuncAttributeMaxDynamicSharedMemorySize, GSMEM);
    cudaFuncSetAttribute(attn_mma, cudaFuncAttributeMaxDynamicSharedMemorySize, A_SMEM);

    to_f16_all<<<8192, 256>>>(x, Wq, Wk, Wv, Wo);

    dim3 gq(24, 16);                       // fused Q,K,V (256-row tiles)
    gemm_qkv<<<gq, 256, GSMEM>>>(bq, bk, bv);

    dim3 ga(S_LEN / AT_Q, N_HEADS);        // (32, 16)
    attn_mma<<<ga, 256, A_SMEM>>>();

    dim3 go(8, 16);
    gemm_out<<<go, 256, GSMEM>>>(bo, out);
}

// round 14
// speedup vs baseline: 1.0264x; 1.0264x over previous
#include <cuda_runtime.h>
#include <cuda_fp16.h>
#include <math.h>

// ---------------- problem constants ----------------
#define S_LEN    4096
#define DMODEL   1024
#define N_HEADS  16
#define HEAD_DIM 64
#define NX (S_LEN * DMODEL)
#define NW (DMODEL * DMODEL)

// ---------------- scratch: single-plane fp16 ----------------
__device__ unsigned short g_x16[NX];
__device__ unsigned short g_q16[NX];
__device__ unsigned short g_k16[NX];
__device__ unsigned short g_v16[NX];
__device__ unsigned short g_c16[NX];
__device__ unsigned short g_Wq16[NW];
__device__ unsigned short g_Wk16[NW];
__device__ unsigned short g_Wv16[NW];
__device__ unsigned short g_Wo16[NW];

// ---------------- small helpers ----------------
__device__ __forceinline__ unsigned smem_u32(const void* p) {
    unsigned a;
    asm("{ .reg .u64 t; cvta.to.shared.u64 t, %1; cvt.u32.u64 %0, t; }" : "=r"(a) : "l"(p));
    return a;
}
__device__ __forceinline__ void cp16(unsigned dst, const void* src) {
    asm volatile("cp.async.cg.shared.global [%0], [%1], 16;" :: "r"(dst), "l"(src));
}
__device__ __forceinline__ void ldm_x4(unsigned* r, unsigned addr) {
    asm volatile("ldmatrix.sync.aligned.m8n8.x4.shared.b16 {%0,%1,%2,%3}, [%4];"
                 : "=r"(r[0]), "=r"(r[1]), "=r"(r[2]), "=r"(r[3]) : "r"(addr));
}
__device__ __forceinline__ void ldm_x4t(unsigned* r, unsigned addr) {
    asm volatile("ldmatrix.sync.aligned.m8n8.x4.trans.shared.b16 {%0,%1,%2,%3}, [%4];"
                 : "=r"(r[0]), "=r"(r[1]), "=r"(r[2]), "=r"(r[3]) : "r"(addr));
}
__device__ __forceinline__ void mma_f16(float* d, const unsigned* a, const unsigned* b) {
    asm volatile(
        "mma.sync.aligned.m16n8k16.row.col.f32.f16.f16.f32 "
        "{%0,%1,%2,%3}, {%4,%5,%6,%7}, {%8,%9}, {%0,%1,%2,%3};"
        : "+f"(d[0]), "+f"(d[1]), "+f"(d[2]), "+f"(d[3])
        : "r"(a[0]), "r"(a[1]), "r"(a[2]), "r"(a[3]), "r"(b[0]), "r"(b[1]));
}
__device__ __forceinline__ unsigned packf16(float lo, float hi) {
    unsigned r;
    asm("cvt.rn.f16x2.f32 %0, %1, %2;" : "=r"(r) : "f"(hi), "f"(lo));
    return r;
}
__device__ __forceinline__ float ex2(float x) {
    float y; asm("ex2.approx.ftz.f32 %0, %1;" : "=f"(y) : "f"(x)); return y;
}
__device__ __forceinline__ float rcp(float x) {
    float y; asm("rcp.approx.ftz.f32 %0, %1;" : "=f"(y) : "f"(x)); return y;
}

// ---------------- convert fp32 -> fp16, 4 independent float4 per thread ----------------
// x: blocks [0,1024), W's: 256 blocks each. Each block converts 4096 floats.
__global__ __launch_bounds__(256)
void to_f16_all(const float* __restrict__ x,
                const float* __restrict__ wq, const float* __restrict__ wk,
                const float* __restrict__ wv, const float* __restrict__ wo)
{
    const int b = blockIdx.x;
    const float* src;
    unsigned short* dst;
    int base;
    if (b < 1024) {
        src = x; dst = g_x16; base = b * 4096;
    } else {
        const int wsel = (b - 1024) >> 8;
        src = (wsel == 0) ? wq : (wsel == 1) ? wk : (wsel == 2) ? wv : wo;
        dst = (wsel == 0) ? g_Wq16 : (wsel == 1) ? g_Wk16 : (wsel == 2) ? g_Wv16 : g_Wo16;
        base = ((b - 1024) & 255) * 4096;
    }
    const int i0 = base + threadIdx.x * 4;
    float4 a0 = *(const float4*)(src + i0);
    float4 a1 = *(const float4*)(src + i0 + 1024);
    float4 a2 = *(const float4*)(src + i0 + 2048);
    float4 a3 = *(const float4*)(src + i0 + 3072);
    *(uint2*)(dst + i0)        = make_uint2(packf16(a0.x, a0.y), packf16(a0.z, a0.w));
    *(uint2*)(dst + i0 + 1024) = make_uint2(packf16(a1.x, a1.y), packf16(a1.z, a1.w));
    *(uint2*)(dst + i0 + 2048) = make_uint2(packf16(a2.x, a2.y), packf16(a2.z, a2.w));
    *(uint2*)(dst + i0 + 3072) = make_uint2(packf16(a3.x, a3.y), packf16(a3.z, a3.w));
}

// ---------------- fp16 GEMM: C = A @ B^T + bias (R12 config) ----------------
// 128x128 tile, BK=32, 8 warps (2x4), warp tile 64x32.
// 4-stage cp.async, single sync per chunk, register fragment double-buffering.
#define ROWB   80
#define PLANE  (128 * ROWB)              // 10240
#define STAGE  (2 * PLANE)               // 20480 (A + B)
#define NSTAGE 4
#define GSMEM  (NSTAGE * STAGE)          // 81920
#define NCHUNK 32

struct Frags {
    unsigned a[4][4];
    unsigned b[2][4];
};

__device__ __forceinline__
void load_frags(Frags& f, unsigned sA, unsigned sB, unsigned ka,
                int a_row, unsigned a_coff, int b_row, unsigned b_coff)
{
#pragma unroll
    for (int pr = 0; pr < 2; pr++)
        ldm_x4(f.b[pr], sB + (unsigned)((b_row + pr * 16) * ROWB) + ka + b_coff);
#pragma unroll
    for (int mt = 0; mt < 4; mt++)
        ldm_x4(f.a[mt], sA + (unsigned)((a_row + mt * 16) * ROWB) + ka + a_coff);
}

__device__ __forceinline__
void do_mma(float acc[4][4][4], const Frags& f)
{
#pragma unroll
    for (int mt = 0; mt < 4; mt++)
#pragma unroll
        for (int pr = 0; pr < 2; pr++)
#pragma unroll
            for (int half = 0; half < 2; half++)
                mma_f16(acc[mt][pr * 2 + half], f.a[mt], &f.b[pr][half * 2]);
}

__device__ __forceinline__
void gemm_body(char* smem,
               const unsigned short* __restrict__ A, const unsigned short* __restrict__ B,
               const float* __restrict__ bias, int bm, int bn,
               int mode, float* __restrict__ C, unsigned short* __restrict__ Ch)
{
    const int t = threadIdx.x, lane = t & 31, wid = t >> 5;
    const int wm = wid >> 2, wn = wid & 3;

    float acc[4][4][4];
#pragma unroll
    for (int mt = 0; mt < 4; mt++)
#pragma unroll
        for (int nt = 0; nt < 4; nt++)
#pragma unroll
            for (int r = 0; r < 4; r++) acc[mt][nt][r] = 0.f;

    const int r0 = t >> 2, s0 = t & 3;
    const int r1 = r0 + 64;

#define ISSUE(cc)                                                                 \
    {                                                                             \
        char* sbuf = smem + ((cc) & (NSTAGE - 1)) * STAGE;                        \
        const int gk = (cc) * 32 + s0 * 8;                                        \
        const unsigned short* ga = A + (size_t)(bm + r0) * DMODEL + gk;           \
        const unsigned short* gb = B + (size_t)(bn + r0) * DMODEL + gk;           \
        unsigned da = smem_u32(sbuf + s0 * 16);                                   \
        unsigned db = smem_u32(sbuf + PLANE + s0 * 16);                           \
        cp16(da + r0 * ROWB, ga);                                                 \
        cp16(da + r1 * ROWB, ga + (size_t)64 * DMODEL);                           \
        cp16(db + r0 * ROWB, gb);                                                 \
        cp16(db + r1 * ROWB, gb + (size_t)64 * DMODEL);                           \
        asm volatile("cp.async.commit_group;" ::: "memory");                      \
    }

    ISSUE(0); ISSUE(1); ISSUE(2);

    const int a_row = wm * 64 + (lane & 15);
    const unsigned a_coff = (lane >> 4) * 16;
    const int b_row = wn * 32 + (lane & 7) + ((lane >> 4) << 3);
    const unsigned b_coff = ((lane >> 3) & 1) * 16;

    // prologue: stages 0 and 1 arrived, then load frags(chunk0, ks0)
    asm volatile("cp.async.wait_group 1;" ::: "memory");
    __syncthreads();

    Frags f0, f1;
    {
        const unsigned sA = smem_u32(smem);
        load_frags(f0, sA, sA + PLANE, 0, a_row, a_coff, b_row, b_coff);
    }

    for (int c = 0; c < NCHUNK; c++) {
        // invariant at top: stages c and c+1 visible to all threads; f0 = (c, ks0)
        if (c + 3 < NCHUNK) ISSUE(c + 3);   // buffer (c+3)%4 == (c-1)%4, freed by last barrier

        const unsigned sA = smem_u32(smem + (c & (NSTAGE - 1)) * STAGE);
        const unsigned sB = sA + PLANE;

        load_frags(f1, sA, sB, 32, a_row, a_coff, b_row, b_coff);   // (c, ks1)
        do_mma(acc, f0);                                            // (c, ks0)

        if (c + 1 < NCHUNK) {
            const unsigned nA = smem_u32(smem + ((c + 1) & (NSTAGE - 1)) * STAGE);
            load_frags(f0, nA, nA + PLANE, 0, a_row, a_coff, b_row, b_coff); // (c+1, ks0)
        }
        do_mma(acc, f1);                                            // (c, ks1)

        if (c + 1 < NCHUNK) {
            if (c + 3 < NCHUNK) {
                asm volatile("cp.async.wait_group 1;" ::: "memory");
            } else {
                asm volatile("cp.async.wait_group 0;" ::: "memory");
            }
            __syncthreads();
        }
    }
#undef ISSUE

    // ---- epilogue ----
    const int er = lane >> 2, ec = (lane & 3) * 2;
#pragma unroll
    for (int mt = 0; mt < 4; mt++) {
        const int row = bm + wm * 64 + mt * 16 + er;
#pragma unroll
        for (int nt = 0; nt < 4; nt++) {
            const int col = bn + wn * 32 + nt * 8 + ec;
            const float b0 = bias[col], b1 = bias[col + 1];
            float v0 = acc[mt][nt][0] + b0, v1 = acc[mt][nt][1] + b1;
            float v2 = acc[mt][nt][2] + b0, v3 = acc[mt][nt][3] + b1;
            if (mode == 0) {
                *(float2*)&C[(size_t)row * DMODEL + col] = make_float2(v0, v1);
                *(float2*)&C[(size_t)(row + 8) * DMODEL + col] = make_float2(v2, v3);
            } else {
                *(unsigned*)&Ch[(size_t)row * DMODEL + col] = packf16(v0, v1);
                *(unsigned*)&Ch[(size_t)(row + 8) * DMODEL + col] = packf16(v2, v3);
            }
        }
    }
}

// ---- fused QKV projection: grid (24, 32); blockIdx.x/8 selects Q/K/V ----
__global__ __launch_bounds__(256, 2)
void gemm_qkv(const float* __restrict__ bq, const float* __restrict__ bk,
              const float* __restrict__ bv)
{
    extern __shared__ char smem[];
    const int which = blockIdx.x >> 3;
    const int bn = (blockIdx.x & 7) * 128;
    const int bm = blockIdx.y * 128;
    const unsigned short* B = (which == 0) ? g_Wq16 : (which == 1) ? g_Wk16 : g_Wv16;
    const float* bias = (which == 0) ? bq : (which == 1) ? bk : bv;
    unsigned short* Ch = (which == 0) ? g_q16 : (which == 1) ? g_k16 : g_v16;
    gemm_body(smem, g_x16, B, bias, bm, bn, 1, nullptr, Ch);
}

// ---- output projection: ctx(f16) @ Wo^T + bo -> fp32 out ----
__global__ __launch_bounds__(256, 2)
void gemm_out(const float* __restrict__ bo, float* __restrict__ out)
{
    extern __shared__ char smem[];
    gemm_body(smem, g_c16, g_Wo16, bo,
              blockIdx.y * 128, blockIdx.x * 128, 0, out, nullptr);
}

// ---------------- tensorized sliding-window attention (fp16) ----------------
// grid (S/128, H), 256 threads (8 warps). Warp w: 16 query rows (local 16w..16w+15),
// keys local [16w, 16w+143] of a shared 256-row K/V tile (9 pr-tiles of 16).
#define AT_Q   128
#define AT_KW  256
#define AROWB  144
#define A_SQ   0
#define A_SK   (AT_Q * AROWB)               // 18432
#define A_SV   (A_SK + AT_KW * AROWB)       // 55296
#define A_SMEM (A_SV + AT_KW * AROWB)       // 92160 -> 2 CTAs/SM

__global__ __launch_bounds__(256, 2)
void attn_mma()
{
    extern __shared__ char smem[];
    const unsigned sb = smem_u32(smem);
    const int t = threadIdx.x, lane = t & 31, w = t >> 5;
    const int h = blockIdx.y;
    const int q0 = blockIdx.x * AT_Q;
    const int j0 = q0 - 64;
    const int col = h * HEAD_DIM;

    // ---- load Q (128x64) ----
#pragma unroll
    for (int i = 0; i < 4; i++) {
        int idx = t + i * 256;               // 0..1023
        int r = idx >> 3, sg = idx & 7;
        *(uint4*)(smem + A_SQ + r * AROWB + sg * 16) =
            *(const uint4*)(g_q16 + (size_t)(q0 + r) * DMODEL + col + sg * 8);
    }
    // ---- load K,V window (256x64), zero-fill out of range ----
#pragma unroll
    for (int i = 0; i < 8; i++) {
        int idx = t + i * 256;               // 0..2047
        int r = idx >> 3, sg = idx & 7;
        int j = j0 + r;
        uint4 kv = make_uint4(0,0,0,0), vv = kv;
        if ((unsigned)j < (unsigned)S_LEN) {
            size_t go = (size_t)j * DMODEL + col + sg * 8;
            kv = *(const uint4*)(g_k16 + go);
            vv = *(const uint4*)(g_v16 + go);
        }
        unsigned so = r * AROWB + sg * 16;
        *(uint4*)(smem + A_SK + so) = kv;
        *(uint4*)(smem + A_SV + so) = vv;
    }
    __syncthreads();

    // ---- S = Q K^T over warp's 144-key window ----
    float sc[18][4];
#pragma unroll
    for (int nt = 0; nt < 18; nt++)
#pragma unroll
        for (int r = 0; r < 4; r++) sc[nt][r] = 0.f;

    const int lk0 = w * 16;
    const unsigned a_base = (unsigned)((w * 16 + (lane & 15)) * AROWB) + ((lane >> 4) << 4);
    const int b_lrow = (lane & 7) + ((lane >> 4) << 3);
    const unsigned b_coff = ((lane >> 3) & 1) << 4;

#pragma unroll
    for (int kc = 0; kc < 4; kc++) {
        unsigned afr[4];
        ldm_x4(afr, sb + A_SQ + a_base + kc * 32);
#pragma unroll
        for (int pr = 0; pr < 9; pr++) {
            unsigned bfr[4];
            ldm_x4(bfr, sb + A_SK + (unsigned)((lk0 + pr * 16 + b_lrow) * AROWB) + kc * 32 + b_coff);
            mma_f16(sc[pr * 2],     afr, &bfr[0]);
            mma_f16(sc[pr * 2 + 1], afr, &bfr[2]);
        }
    }

    // ---- mask + softmax ----
    const int er = lane >> 2, ec = (lane & 3) * 2;
    const float SC = 0.125f * 1.44269504088896f;
    float m0 = -1e30f, m1 = -1e30f;
#pragma unroll
    for (int nt = 0; nt < 18; nt++) {
        const int d = nt * 8 + ec;
        const int j = j0 + lk0 + d;
        bool v00 = ((unsigned)(d     - er)     <= 128u) && ((unsigned)j       < (unsigned)S_LEN);
        bool v01 = ((unsigned)(d + 1 - er)     <= 128u) && ((unsigned)(j + 1) < (unsigned)S_LEN);
        bool v10 = ((unsigned)(d     - er - 8) <= 128u) && ((unsigned)j       < (unsigned)S_LEN);
        bool v11 = ((unsigned)(d + 1 - er - 8) <= 128u) && ((unsigned)(j + 1) < (unsigned)S_LEN);
        sc[nt][0] = v00 ? sc[nt][0] * SC : -1e30f;
        sc[nt][1] = v01 ? sc[nt][1] * SC : -1e30f;
        sc[nt][2] = v10 ? sc[nt][2] * SC : -1e30f;
        sc[nt][3] = v11 ? sc[nt][3] * SC : -1e30f;
        m0 = fmaxf(m0, fmaxf(sc[nt][0], sc[nt][1]));
        m1 = fmaxf(m1, fmaxf(sc[nt][2], sc[nt][3]));
    }
    m0 = fmaxf(m0, __shfl_xor_sync(0xffffffffu, m0, 1));
    m0 = fmaxf(m0, __shfl_xor_sync(0xffffffffu, m0, 2));
    m1 = fmaxf(m1, __shfl_xor_sync(0xffffffffu, m1, 1));
    m1 = fmaxf(m1, __shfl_xor_sync(0xffffffffu, m1, 2));

    float s0 = 0.f, s1 = 0.f;
#pragma unroll
    for (int nt = 0; nt < 18; nt++) {
        sc[nt][0] = ex2(sc[nt][0] - m0);
        sc[nt][1] = ex2(sc[nt][1] - m0);
        sc[nt][2] = ex2(sc[nt][2] - m1);
        sc[nt][3] = ex2(sc[nt][3] - m1);
        s0 += sc[nt][0] + sc[nt][1];
        s1 += sc[nt][2] + sc[nt][3];
    }
    s0 += __shfl_xor_sync(0xffffffffu, s0, 1);
    s0 += __shfl_xor_sync(0xffffffffu, s0, 2);
    s1 += __shfl_xor_sync(0xffffffffu, s1, 1);
    s1 += __shfl_xor_sync(0xffffffffu, s1, 2);
    const float inv0 = rcp(s0), inv1 = rcp(s1);

    // ---- O = P V over the same 144-key window ----
    float oa[8][4];
#pragma unroll
    for (int nt = 0; nt < 8; nt++)
#pragma unroll
        for (int r = 0; r < 4; r++) oa[nt][r] = 0.f;

#pragma unroll
    for (int kc = 0; kc < 9; kc++) {
        unsigned ph[4];
        ph[0] = packf16(sc[2 * kc][0],     sc[2 * kc][1]);
        ph[1] = packf16(sc[2 * kc][2],     sc[2 * kc][3]);
        ph[2] = packf16(sc[2 * kc + 1][0], sc[2 * kc + 1][1]);
        ph[3] = packf16(sc[2 * kc + 1][2], sc[2 * kc + 1][3]);
#pragma unroll
        for (int dt = 0; dt < 4; dt++) {
            unsigned vh[4];
            unsigned voff = (unsigned)((lk0 + kc * 16 + (lane & 15)) * AROWB) + dt * 32 + ((lane >> 4) << 4);
            ldm_x4t(vh, sb + A_SV + voff);
            mma_f16(oa[2 * dt],     ph, &vh[0]);
            mma_f16(oa[2 * dt + 1], ph, &vh[2]);
        }
    }

    // ---- normalize + write ctx as fp16 ----
    const int row0 = q0 + w * 16 + er;
#pragma unroll
    for (int nt = 0; nt < 8; nt++) {
        const int oc = col + nt * 8 + ec;
        float v0 = oa[nt][0] * inv0, v1 = oa[nt][1] * inv0;
        float v2 = oa[nt][2] * inv1, v3 = oa[nt][3] * inv1;
        *(unsigned*)&g_c16[(size_t)row0 * DMODEL + oc] = packf16(v0, v1);
        *(unsigned*)&g_c16[(size_t)(row0 + 8) * DMODEL + oc] = packf16(v2, v3);
    }
}

// ---------------- launch ----------------
extern "C" void kernel_launch(void* const* d_in, const int* in_sizes, int n_in,
                              void* d_out, int out_size)
{
    const float* x  = (const float*)d_in[0];
    const float* Wq = (const float*)d_in[1];
    const float* bq = (const float*)d_in[2];
    const float* Wk = (const float*)d_in[3];
    const float* bk = (const float*)d_in[4];
    const float* Wv = (const float*)d_in[5];
    const float* bv = (const float*)d_in[6];
    const float* Wo = (const float*)d_in[7];
    const float* bo = (const float*)d_in[8];
    float* out = (float*)d_out;

    cudaFuncSetAttribute(gemm_qkv, cudaFuncAttributeMaxDynamicSharedMemorySize, GSMEM);
    cudaFuncSetAttribute(gemm_out, cudaFuncAttributeMaxDynamicSharedMemorySize, GSMEM);
    cudaFuncSetAttribute(attn_mma, cudaFuncAttributeMaxDynamicSharedMemorySize, A_SMEM);

    to_f16_all<<<2048, 256>>>(x, Wq, Wk, Wv, Wo);

    dim3 gq(24, 32);                       // fused Q,K,V
    gemm_qkv<<<gq, 256, GSMEM>>>(bq, bk, bv);

    dim3 ga(S_LEN / AT_Q, N_HEADS);        // (32, 16)
    attn_mma<<<ga, 256, A_SMEM>>>();

    dim3 go(8, 32);
    gemm_out<<<go, 256, GSMEM>>>(bo, out);
}